// round 1
// baseline (speedup 1.0000x reference)
#include <cuda_runtime.h>
#include <math.h>

// Problem constants (fixed shapes per reference)
#define TT 2048   // tokens (B*S)
#define HH 2048   // hidden
#define II 5632   // intermediate
#define EE 8      // experts
#define CAP 2048  // per-expert row capacity (worst case: every token picks this expert once)

// ---------------- scratch (device globals; no allocations allowed) ----------------
__device__ int   g_count[EE];                    // rows assigned per expert
__device__ int   g_row_token[EE * CAP];          // perm row -> token index (0-filled for inactive)
__device__ int   g_token_row[TT * 2];            // token -> its two perm rows
__device__ float g_token_w[TT * 2];              // token -> its two renormalized weights
__device__ float g_act[92274688];                // [EE*CAP, II]  (8*2048*5632) = 369MB
__device__ float g_y  [33554432];                // [EE*CAP, HH]  (8*2048*2048) = 134MB

// ---------------- init ----------------
__global__ void init_kernel() {
    int i = blockIdx.x * blockDim.x + threadIdx.x;
    if (i < EE) g_count[i] = 0;
    if (i < EE * CAP) g_row_token[i] = 0;
}

// ---------------- router: logits -> softmax top2 -> renorm weights + assignment ----------------
__global__ void router_kernel(const float* __restrict__ x, const float* __restrict__ gw) {
    int t = blockIdx.x;
    const float* xr = x + (size_t)t * HH;
    float acc[EE];
#pragma unroll
    for (int e = 0; e < EE; e++) acc[e] = 0.f;
    for (int k = threadIdx.x; k < HH; k += blockDim.x) {
        float xv = xr[k];
#pragma unroll
        for (int e = 0; e < EE; e++) acc[e] += xv * gw[e * HH + k];
    }
    __shared__ float red[EE][128];
#pragma unroll
    for (int e = 0; e < EE; e++) red[e][threadIdx.x] = acc[e];
    __syncthreads();
    for (int s = 64; s > 0; s >>= 1) {
        if (threadIdx.x < s) {
#pragma unroll
            for (int e = 0; e < EE; e++) red[e][threadIdx.x] += red[e][threadIdx.x + s];
        }
        __syncthreads();
    }
    if (threadIdx.x == 0) {
        float l[EE];
#pragma unroll
        for (int e = 0; e < EE; e++) l[e] = red[e][0];
        // top-2 by logit (softmax is monotonic); ties -> lower index (matches jax top_k)
        int i0 = 0;
#pragma unroll
        for (int e = 1; e < EE; e++) if (l[e] > l[i0]) i0 = e;
        int i1 = (i0 == 0) ? 1 : 0;
#pragma unroll
        for (int e = 0; e < EE; e++) if (e != i0 && l[e] > l[i1]) i1 = e;
        // renormalized weights over the pair: w0 = p0/(p0+p1) = 1/(1+exp(l1-l0))
        float w0 = 1.f / (1.f + expf(l[i1] - l[i0]));
        float w1 = 1.f - w0;
        int p0 = atomicAdd(&g_count[i0], 1);
        int p1 = atomicAdd(&g_count[i1], 1);
        g_row_token[i0 * CAP + p0] = t;
        g_row_token[i1 * CAP + p1] = t;
        g_token_row[t * 2 + 0] = i0 * CAP + p0;
        g_token_row[t * 2 + 1] = i1 * CAP + p1;
        g_token_w[t * 2 + 0] = w0;
        g_token_w[t * 2 + 1] = w1;
    }
}

// ---------------- tiled SGEMM: C[m,n] = sum_k A[m,k] * W[e][n,k] ----------------
// GATHER=1: A rows gathered from x via g_row_token; else A = g_act direct rows.
// MODE 0: C = g_act, store raw (gate pass, N=II, K=HH)
// MODE 1: C = g_act, store silu(prevC)*acc (up pass fused, N=II, K=HH)
// MODE 2: C = g_y, store raw (down pass, N=HH, K=II)
template <int GATHER, int MODE>
__global__ void __launch_bounds__(256, 2) sgemm_kernel(const float* __restrict__ Aparam,
                                                       const float* __restrict__ Wglob) {
    const int BM = 128, BN = 128, BK = 8;
    const int N  = (MODE == 2) ? HH : II;
    const int Kd = (MODE == 2) ? II : HH;

    int e   = blockIdx.z;
    int cnt = g_count[e];
    int m0  = blockIdx.y * BM;
    if (m0 >= cnt) return;                       // skip empty row tiles
    int n0  = blockIdx.x * BN;

    const float* W = Wglob + (size_t)e * N * Kd;
    float* C = (MODE == 2) ? g_y : g_act;

    __shared__ float As[BK][BM];
    __shared__ float Bs[BK][BN];
    __shared__ const float* Arow[BM];

    int tid = threadIdx.x;
    if (tid < BM) {
        size_t r;
        if (GATHER) r = (size_t)g_row_token[e * CAP + m0 + tid];
        else        r = (size_t)(e * CAP + m0 + tid);
        Arow[tid] = (GATHER ? Aparam : g_act) + r * Kd;
    }
    __syncthreads();

    int aRow = tid >> 1;           // 0..127
    int aCol = (tid & 1) << 2;     // 0 or 4
    const float* arow = Arow[aRow] + aCol;
    const float* wrow = W + (size_t)(n0 + aRow) * Kd + aCol;

    int ty = tid >> 4;             // 0..15
    int tx = tid & 15;             // 0..15

    float acc[8][8];
#pragma unroll
    for (int i = 0; i < 8; i++)
#pragma unroll
        for (int j = 0; j < 8; j++) acc[i][j] = 0.f;

    for (int k0 = 0; k0 < Kd; k0 += BK) {
        float4 av = *(const float4*)(arow + k0);
        float4 bv = *(const float4*)(wrow + k0);
        As[aCol + 0][aRow] = av.x; As[aCol + 1][aRow] = av.y;
        As[aCol + 2][aRow] = av.z; As[aCol + 3][aRow] = av.w;
        Bs[aCol + 0][aRow] = bv.x; Bs[aCol + 1][aRow] = bv.y;
        Bs[aCol + 2][aRow] = bv.z; Bs[aCol + 3][aRow] = bv.w;
        __syncthreads();
#pragma unroll
        for (int k = 0; k < BK; k++) {
            float4 a0 = *(const float4*)&As[k][ty * 8];
            float4 a1 = *(const float4*)&As[k][ty * 8 + 4];
            float4 b0 = *(const float4*)&Bs[k][tx * 8];
            float4 b1 = *(const float4*)&Bs[k][tx * 8 + 4];
            float a[8] = {a0.x, a0.y, a0.z, a0.w, a1.x, a1.y, a1.z, a1.w};
            float b[8] = {b0.x, b0.y, b0.z, b0.w, b1.x, b1.y, b1.z, b1.w};
#pragma unroll
            for (int i = 0; i < 8; i++)
#pragma unroll
                for (int j = 0; j < 8; j++) acc[i][j] += a[i] * b[j];
        }
        __syncthreads();
    }

    // epilogue
#pragma unroll
    for (int i = 0; i < 8; i++) {
        int m = m0 + ty * 8 + i;
        size_t crow = (size_t)(e * CAP + m) * N + n0 + tx * 8;
#pragma unroll
        for (int j = 0; j < 8; j++) {
            float v = acc[i][j];
            if (MODE == 1) {
                float g = C[crow + j];
                float s = g / (1.f + expf(-g));   // silu(g)
                v = s * v;                         // silu(gate) * up
            }
            C[crow + j] = v;
        }
    }
}

// ---------------- combine: out[t,h] = w0*y[row0,h] + w1*y[row1,h] ----------------
__global__ void combine_kernel(float* __restrict__ out) {
    int idx = blockIdx.x * blockDim.x + threadIdx.x;
    if (idx >= TT * HH) return;
    int t = idx >> 11;             // / HH (2048)
    int h = idx & (HH - 1);
    int r0 = g_token_row[t * 2 + 0];
    int r1 = g_token_row[t * 2 + 1];
    float w0 = g_token_w[t * 2 + 0];
    float w1 = g_token_w[t * 2 + 1];
    out[idx] = w0 * g_y[(size_t)r0 * HH + h] + w1 * g_y[(size_t)r1 * HH + h];
}

// ---------------- launch ----------------
extern "C" void kernel_launch(void* const* d_in, const int* in_sizes, int n_in,
                              void* d_out, int out_size) {
    const float* x  = (const float*)d_in[0];  // [1,2048,2048]
    const float* gw = (const float*)d_in[1];  // [8,2048]
    const float* wg = (const float*)d_in[2];  // [8,5632,2048]
    const float* wu = (const float*)d_in[3];  // [8,5632,2048]
    const float* wd = (const float*)d_in[4];  // [8,2048,5632]
    float* out = (float*)d_out;               // [1,2048,2048] fp32
    (void)in_sizes; (void)n_in; (void)out_size;

    init_kernel<<<64, 256>>>();
    router_kernel<<<TT, 128>>>(x, gw);

    dim3 g1(II / 128, CAP / 128, EE);   // (44,16,8)
    sgemm_kernel<1, 0><<<g1, 256>>>(x, wg);  // g = Xe @ Wg^T
    sgemm_kernel<1, 1><<<g1, 256>>>(x, wu);  // act = silu(g) * (Xe @ Wu^T)

    dim3 g2(HH / 128, CAP / 128, EE);   // (16,16,8)
    sgemm_kernel<0, 2><<<g2, 256>>>(nullptr, wd);  // y = act @ Wd^T

    combine_kernel<<<(TT * HH + 255) / 256, 256>>>(out);
}

// round 6
// speedup vs baseline: 2.6127x; 2.6127x over previous
#include <cuda_runtime.h>
#include <cstdint>
#include <math.h>

// ---------------- problem constants ----------------
#define TT 2048   // tokens
#define HH 2048   // hidden
#define II 5632   // intermediate
#define EE 8      // experts
#define CAP 2048  // per-expert row capacity

// ---------------- scratch ----------------
__device__ int   g_count[EE];
__device__ int   g_row_token[EE * CAP];
__device__ int   g_token_row[TT * 2];
__device__ float g_token_w[TT * 2];
__device__ float g_act[(size_t)EE * CAP * II];   // 369MB
__device__ float g_y  [(size_t)EE * CAP * HH];   // 134MB

// ---------------- helpers ----------------
__device__ __forceinline__ uint32_t f2tf32(float f) {
    uint32_t u;
    asm("cvt.rna.tf32.f32 %0, %1;" : "=r"(u) : "f"(f));
    return u;
}
// D = A(16x8) * B(8x8) + D, tf32 inputs, f32 accumulate
__device__ __forceinline__ void mma_tf32(float* c, const uint32_t* a, const uint32_t* b) {
    asm volatile(
        "mma.sync.aligned.m16n8k8.row.col.f32.tf32.tf32.f32 "
        "{%0,%1,%2,%3}, {%4,%5,%6,%7}, {%8,%9}, {%0,%1,%2,%3};"
        : "+f"(c[0]), "+f"(c[1]), "+f"(c[2]), "+f"(c[3])
        : "r"(a[0]), "r"(a[1]), "r"(a[2]), "r"(a[3]), "r"(b[0]), "r"(b[1]));
}

// ---------------- init ----------------
__global__ void init_kernel() {
    int i = blockIdx.x * blockDim.x + threadIdx.x;
    if (i < EE) g_count[i] = 0;
    if (i < EE * CAP) g_row_token[i] = 0;
}

// ---------------- router ----------------
__global__ void router_kernel(const float* __restrict__ x, const float* __restrict__ gw) {
    int t = blockIdx.x;
    const float* xr = x + (size_t)t * HH;
    float acc[EE];
#pragma unroll
    for (int e = 0; e < EE; e++) acc[e] = 0.f;
    for (int k = threadIdx.x; k < HH; k += blockDim.x) {
        float xv = xr[k];
#pragma unroll
        for (int e = 0; e < EE; e++) acc[e] += xv * gw[e * HH + k];
    }
    __shared__ float red[EE][128];
#pragma unroll
    for (int e = 0; e < EE; e++) red[e][threadIdx.x] = acc[e];
    __syncthreads();
    for (int s = 64; s > 0; s >>= 1) {
        if (threadIdx.x < s) {
#pragma unroll
            for (int e = 0; e < EE; e++) red[e][threadIdx.x] += red[e][threadIdx.x + s];
        }
        __syncthreads();
    }
    if (threadIdx.x == 0) {
        float l[EE];
#pragma unroll
        for (int e = 0; e < EE; e++) l[e] = red[e][0];
        int i0 = 0;
#pragma unroll
        for (int e = 1; e < EE; e++) if (l[e] > l[i0]) i0 = e;
        int i1 = (i0 == 0) ? 1 : 0;
#pragma unroll
        for (int e = 0; e < EE; e++) if (e != i0 && l[e] > l[i1]) i1 = e;
        float w0 = 1.f / (1.f + expf(l[i1] - l[i0]));
        float w1 = 1.f - w0;
        int p0 = atomicAdd(&g_count[i0], 1);
        int p1 = atomicAdd(&g_count[i1], 1);
        g_row_token[i0 * CAP + p0] = t;
        g_row_token[i1 * CAP + p1] = t;
        g_token_row[t * 2 + 0] = i0 * CAP + p0;
        g_token_row[t * 2 + 1] = i1 * CAP + p1;
        g_token_w[t * 2 + 0] = w0;
        g_token_w[t * 2 + 1] = w1;
    }
}

// ---------------- TF32 mma.sync GEMM: C[m,n] = sum_k A[m,k] * W[e][n,k] ----------------
// BM=BN=128, BK=16. 256 threads = 8 warps in 2(M) x 4(N); warp tile 64x32.
// GATHER=1: A rows gathered from X via g_row_token.
// MODE 0: gate -> g_act raw. MODE 1: up -> g_act = silu(g_act)*acc. MODE 2: down -> g_y raw.
#define SPITCH 20   // smem row stride in floats (16 + 4 pad -> conflict-free fragment reads)

template <int GATHER, int MODE>
__global__ void __launch_bounds__(256, 2)
mma_gemm_kernel(const float* __restrict__ X, const float* __restrict__ Wglob) {
    constexpr int N  = (MODE == 2) ? HH : II;
    constexpr int Kd = (MODE == 2) ? II : HH;
    constexpr int NT = Kd / 16;

    __shared__ uint32_t As[2][128 * SPITCH];
    __shared__ uint32_t Bs[2][128 * SPITCH];

    const int e   = blockIdx.z;
    const int cnt = g_count[e];
    const int m0  = blockIdx.y * 128;
    if (m0 >= cnt) return;
    const int n0  = blockIdx.x * 128;

    const int tid  = threadIdx.x;
    const int lane = tid & 31;
    const int wid  = tid >> 5;
    const int wm   = wid >> 2;   // 0..1  (M)
    const int wn   = wid & 3;    // 0..3  (N)
    const int gid  = lane >> 2;  // 0..7
    const int tig  = lane & 3;   // 0..3

    const float* W = Wglob + (size_t)e * N * Kd;
    float* C = (MODE == 2) ? g_y : g_act;

    // ---- global load mapping: thread covers rows lr and lr+64, float4 at col lk ----
    const int lr = tid >> 2;        // 0..63
    const int lk = (tid & 3) * 4;   // 0,4,8,12
    size_t ar0, ar1;
    if (GATHER) {
        ar0 = (size_t)g_row_token[e * CAP + m0 + lr];
        ar1 = (size_t)g_row_token[e * CAP + m0 + lr + 64];
    } else {
        ar0 = (size_t)(e * CAP + m0 + lr);
        ar1 = (size_t)(e * CAP + m0 + lr + 64);
    }
    const float* Abase = GATHER ? X : g_act;
    const float* aP0 = Abase + ar0 * Kd + lk;
    const float* aP1 = Abase + ar1 * Kd + lk;
    const float* bP0 = W + (size_t)(n0 + lr) * Kd + lk;
    const float* bP1 = W + (size_t)(n0 + lr + 64) * Kd + lk;
    const int sO0 = lr * SPITCH + lk;
    const int sO1 = (lr + 64) * SPITCH + lk;

    // ---- prologue: tile 0 -> buffer 0 ----
    {
        float4 va0 = *(const float4*)aP0;
        float4 va1 = *(const float4*)aP1;
        float4 vb0 = *(const float4*)bP0;
        float4 vb1 = *(const float4*)bP1;
        *(uint4*)&As[0][sO0] = make_uint4(f2tf32(va0.x), f2tf32(va0.y), f2tf32(va0.z), f2tf32(va0.w));
        *(uint4*)&As[0][sO1] = make_uint4(f2tf32(va1.x), f2tf32(va1.y), f2tf32(va1.z), f2tf32(va1.w));
        *(uint4*)&Bs[0][sO0] = make_uint4(f2tf32(vb0.x), f2tf32(vb0.y), f2tf32(vb0.z), f2tf32(vb0.w));
        *(uint4*)&Bs[0][sO1] = make_uint4(f2tf32(vb1.x), f2tf32(vb1.y), f2tf32(vb1.z), f2tf32(vb1.w));
    }
    __syncthreads();

    float c[4][4][4];
#pragma unroll
    for (int mt = 0; mt < 4; mt++)
#pragma unroll
        for (int nt = 0; nt < 4; nt++)
#pragma unroll
            for (int i = 0; i < 4; i++) c[mt][nt][i] = 0.f;

    const int aRowBase = wm * 64 + gid;  // + mt*16 (+8)
    const int bRowBase = wn * 32 + gid;  // + nt*8

    for (int it = 0; it < NT; ++it) {
        const int cur = it & 1;
        const bool more = (it + 1 < NT);
        float4 va0, va1, vb0, vb1;
        if (more) {
            const int k0 = (it + 1) * 16;
            va0 = *(const float4*)(aP0 + k0);
            va1 = *(const float4*)(aP1 + k0);
            vb0 = *(const float4*)(bP0 + k0);
            vb1 = *(const float4*)(bP1 + k0);
        }
        const uint32_t* Ac = As[cur];
        const uint32_t* Bc = Bs[cur];
#pragma unroll
        for (int K = 0; K < 2; K++) {
            const int kc = K * 8 + tig;
            uint32_t af[4][4];
#pragma unroll
            for (int mt = 0; mt < 4; mt++) {
                const int r = (aRowBase + mt * 16) * SPITCH + kc;
                af[mt][0] = Ac[r];
                af[mt][1] = Ac[r + 8 * SPITCH];
                af[mt][2] = Ac[r + 4];
                af[mt][3] = Ac[r + 8 * SPITCH + 4];
            }
            uint32_t bf[4][2];
#pragma unroll
            for (int nt = 0; nt < 4; nt++) {
                const int r = (bRowBase + nt * 8) * SPITCH + kc;
                bf[nt][0] = Bc[r];
                bf[nt][1] = Bc[r + 4];
            }
#pragma unroll
            for (int mt = 0; mt < 4; mt++)
#pragma unroll
                for (int nt = 0; nt < 4; nt++)
                    mma_tf32(c[mt][nt], af[mt], bf[nt]);
        }
        if (more) {
            const int nb = cur ^ 1;
            *(uint4*)&As[nb][sO0] = make_uint4(f2tf32(va0.x), f2tf32(va0.y), f2tf32(va0.z), f2tf32(va0.w));
            *(uint4*)&As[nb][sO1] = make_uint4(f2tf32(va1.x), f2tf32(va1.y), f2tf32(va1.z), f2tf32(va1.w));
            *(uint4*)&Bs[nb][sO0] = make_uint4(f2tf32(vb0.x), f2tf32(vb0.y), f2tf32(vb0.z), f2tf32(vb0.w));
            *(uint4*)&Bs[nb][sO1] = make_uint4(f2tf32(vb1.x), f2tf32(vb1.y), f2tf32(vb1.z), f2tf32(vb1.w));
        }
        __syncthreads();
    }

    // ---- epilogue ----
#pragma unroll
    for (int mt = 0; mt < 4; mt++) {
        const int row = m0 + wm * 64 + mt * 16 + gid;
#pragma unroll
        for (int nt = 0; nt < 4; nt++) {
            const int col = n0 + wn * 32 + nt * 8 + 2 * tig;
            size_t b0 = (size_t)(e * CAP + row) * N + col;
            size_t b1 = b0 + (size_t)8 * N;
            float2 v0 = make_float2(c[mt][nt][0], c[mt][nt][1]);
            float2 v1 = make_float2(c[mt][nt][2], c[mt][nt][3]);
            if (MODE == 1) {
                float2 ga = *(const float2*)&C[b0];
                float2 gb = *(const float2*)&C[b1];
                v0.x *= ga.x / (1.f + expf(-ga.x));
                v0.y *= ga.y / (1.f + expf(-ga.y));
                v1.x *= gb.x / (1.f + expf(-gb.x));
                v1.y *= gb.y / (1.f + expf(-gb.y));
            }
            *(float2*)&C[b0] = v0;
            *(float2*)&C[b1] = v1;
        }
    }
}

// ---------------- combine ----------------
__global__ void combine_kernel(float* __restrict__ out) {
    int idx = blockIdx.x * blockDim.x + threadIdx.x;
    if (idx >= TT * HH) return;
    int t = idx >> 11;
    int h = idx & (HH - 1);
    int r0 = g_token_row[t * 2 + 0];
    int r1 = g_token_row[t * 2 + 1];
    float w0 = g_token_w[t * 2 + 0];
    float w1 = g_token_w[t * 2 + 1];
    out[idx] = w0 * g_y[(size_t)r0 * HH + h] + w1 * g_y[(size_t)r1 * HH + h];
}

// ---------------- launch ----------------
extern "C" void kernel_launch(void* const* d_in, const int* in_sizes, int n_in,
                              void* d_out, int out_size) {
    const float* x  = (const float*)d_in[0];
    const float* gw = (const float*)d_in[1];
    const float* wg = (const float*)d_in[2];
    const float* wu = (const float*)d_in[3];
    const float* wd = (const float*)d_in[4];
    float* out = (float*)d_out;
    (void)in_sizes; (void)n_in; (void)out_size;

    init_kernel<<<64, 256>>>();
    router_kernel<<<TT, 128>>>(x, gw);

    dim3 g1(II / 128, CAP / 128, EE);   // (44,16,8)
    mma_gemm_kernel<1, 0><<<g1, 256>>>(x, wg);   // g = Xe @ Wg^T
    mma_gemm_kernel<1, 1><<<g1, 256>>>(x, wu);   // act = silu(g) * (Xe @ Wu^T)

    dim3 g2(HH / 128, CAP / 128, EE);   // (16,16,8)
    mma_gemm_kernel<0, 2><<<g2, 256>>>(nullptr, wd);  // y = act @ Wd^T

    combine_kernel<<<(TT * HH + 255) / 256, 256>>>(out);
}